// round 5
// baseline (speedup 1.0000x reference)
#include <cuda_runtime.h>
#include <cstdint>
#include <cstddef>

#define DIM      256
#define KC       1024
#define ROWS     32
#define DK       16
#define NTHREADS 256

__device__ float g_cnorm[KC];
__device__ float g_partials[4096];

__device__ __forceinline__ void cpa16(void* sdst, const void* gsrc) {
    uint32_t s = (uint32_t)__cvta_generic_to_shared(sdst);
    asm volatile("cp.async.ca.shared.global [%0], [%1], 16;\n" :: "r"(s), "l"(gsrc));
}
__device__ __forceinline__ float frcp(float x) {
    float r; asm("rcp.approx.ftz.f32 %0, %1;" : "=f"(r) : "f"(x)); return r;
}

// ---------------------------------------------------------------- codebook column norms
__global__ void cnorm_kernel(const float* __restrict__ cb) {
    int col = blockIdx.x * blockDim.x + threadIdx.x;
    if (col < KC) {
        float s = 0.f;
        #pragma unroll 8
        for (int d = 0; d < DIM; ++d) { float v = cb[d * KC + col]; s = fmaf(v, v, s); }
        g_cnorm[col] = s;
    }
}

// ---------------------------------------------------------------- fused VQ kernel
// CTA: 32 rows x 1024 codes. Thread tile: 4 rows x 32 cols (cols = g*128 + 4*lane + k).
__global__ __launch_bounds__(NTHREADS, 1)
void vq_main(const float* __restrict__ x, const float* __restrict__ cb,
             float* __restrict__ qout, float* __restrict__ scout) {
    extern __shared__ float sm[];
    float* Xs = sm;                 // ROWS*DIM   = 8192 floats
    float* CN = Xs + ROWS * DIM;    // KC         = 1024 floats
    float* Ct = CN + KC;            // 2*DK*KC    = 32768 floats
    __shared__ float wl[8];

    const int tid  = threadIdx.x;
    const int warp = tid >> 5, lane = tid & 31;
    const int row0 = blockIdx.x * ROWS;

    // Load X tile (32 rows x 256 = one contiguous 32KB block)
    {
        const float4* src = (const float4*)(x + (size_t)row0 * DIM);
        float4* dst = (float4*)Xs;
        #pragma unroll
        for (int i = 0; i < 8; ++i) dst[tid + i * NTHREADS] = src[tid + i * NTHREADS];
    }
    #pragma unroll
    for (int i = 0; i < 4; ++i) CN[tid + i * NTHREADS] = g_cnorm[tid + i * NTHREADS];
    __syncthreads();

    // Per-row ||x||^2 (warp w owns rows 4w..4w+3)
    float xn[4];
    #pragma unroll
    for (int r = 0; r < 4; ++r) {
        const float* xr = Xs + (warp * 4 + r) * DIM;
        float s = 0.f;
        #pragma unroll
        for (int i = 0; i < 8; ++i) { float v = xr[lane + 32 * i]; s = fmaf(v, v, s); }
        #pragma unroll
        for (int o = 16; o; o >>= 1) s += __shfl_xor_sync(0xffffffffu, s, o);
        xn[r] = s;
    }

    float4 acc[4][8];
    #pragma unroll
    for (int r = 0; r < 4; ++r)
        #pragma unroll
        for (int g = 0; g < 8; ++g) acc[r][g] = make_float4(0.f, 0.f, 0.f, 0.f);

    // Prologue: async-load codebook chunk 0
    {
        const float4* src = (const float4*)cb;
        float4* dst = (float4*)Ct;
        #pragma unroll
        for (int i = 0; i < 16; ++i) cpa16(dst + tid + i * NTHREADS, src + tid + i * NTHREADS);
        asm volatile("cp.async.commit_group;\n");
    }

    const int NCHUNK = DIM / DK;   // 16
    for (int c = 0; c < NCHUNK; ++c) {
        if (c + 1 < NCHUNK) {
            const float4* src = (const float4*)(cb + (size_t)(c + 1) * DK * KC);
            float4* dst = (float4*)(Ct + ((c + 1) & 1) * DK * KC);
            #pragma unroll
            for (int i = 0; i < 16; ++i) cpa16(dst + tid + i * NTHREADS, src + tid + i * NTHREADS);
            asm volatile("cp.async.commit_group;\n");
            asm volatile("cp.async.wait_group 1;\n");
        } else {
            asm volatile("cp.async.wait_group 0;\n");
        }
        __syncthreads();

        const float* B  = Ct + (c & 1) * DK * KC;
        const float* Xb = Xs + warp * 4 * DIM + c * DK;
        #pragma unroll 4
        for (int dd = 0; dd < DK; ++dd) {
            float a0 = Xb[dd];
            float a1 = Xb[DIM + dd];
            float a2 = Xb[2 * DIM + dd];
            float a3 = Xb[3 * DIM + dd];
            const float4* Bd = (const float4*)(B + dd * KC);
            #pragma unroll
            for (int g = 0; g < 8; ++g) {
                float4 b = Bd[g * 32 + lane];
                acc[0][g].x = fmaf(a0, b.x, acc[0][g].x); acc[0][g].y = fmaf(a0, b.y, acc[0][g].y);
                acc[0][g].z = fmaf(a0, b.z, acc[0][g].z); acc[0][g].w = fmaf(a0, b.w, acc[0][g].w);
                acc[1][g].x = fmaf(a1, b.x, acc[1][g].x); acc[1][g].y = fmaf(a1, b.y, acc[1][g].y);
                acc[1][g].z = fmaf(a1, b.z, acc[1][g].z); acc[1][g].w = fmaf(a1, b.w, acc[1][g].w);
                acc[2][g].x = fmaf(a2, b.x, acc[2][g].x); acc[2][g].y = fmaf(a2, b.y, acc[2][g].y);
                acc[2][g].z = fmaf(a2, b.z, acc[2][g].z); acc[2][g].w = fmaf(a2, b.w, acc[2][g].w);
                acc[3][g].x = fmaf(a3, b.x, acc[3][g].x); acc[3][g].y = fmaf(a3, b.y, acc[3][g].y);
                acc[3][g].z = fmaf(a3, b.z, acc[3][g].z); acc[3][g].w = fmaf(a3, b.w, acc[3][g].w);
            }
        }
        __syncthreads();
    }

    // Codebook col norms for this lane's columns
    float4 cn4[8];
    #pragma unroll
    for (int g = 0; g < 8; ++g) cn4[g] = ((const float4*)CN)[g * 32 + lane];

    float warploss = 0.f;
    #pragma unroll
    for (int r = 0; r < 4; ++r) {
        const int row = warp * 4 + r;
        const float xnr = xn[r];
        float dmin = 3.4e38f; int didx = 0;

        // sim -> dist (in place). Ascending col order within lane + strict '<'
        // keeps the lowest tied index (matches jnp.argmin).
        #pragma unroll
        for (int g = 0; g < 8; ++g) {
            float4 d4 = acc[r][g];
            float4 c4 = cn4[g];
            int cbse = g * 128 + lane * 4;
            d4.x = fmaf(-2.f, d4.x, xnr + c4.x);
            d4.y = fmaf(-2.f, d4.y, xnr + c4.y);
            d4.z = fmaf(-2.f, d4.z, xnr + c4.z);
            d4.w = fmaf(-2.f, d4.w, xnr + c4.w);
            if (d4.x < dmin) { dmin = d4.x; didx = cbse + 0; }
            if (d4.y < dmin) { dmin = d4.y; didx = cbse + 1; }
            if (d4.z < dmin) { dmin = d4.z; didx = cbse + 2; }
            if (d4.w < dmin) { dmin = d4.w; didx = cbse + 3; }
            acc[r][g] = d4;
        }

        // Batched reciprocal: 1 MUFU per 8 values, then inv^2, accumulate row sum.
        float lsum = 0.f;
        #pragma unroll
        for (int g = 0; g < 8; g += 2) {
            float4 A = acc[r][g], B4 = acc[r][g + 1];
            float pa = A.x * A.y, pb = A.z * A.w, pc = B4.x * B4.y, pd = B4.z * B4.w;
            float pab = pa * pb, pcd = pc * pd;
            float R   = frcp(pab * pcd);
            float rab = pcd * R, rcd = pab * R;          // 1/pab, 1/pcd
            float ra  = pb * rab, rb = pa * rab;          // 1/pa, 1/pb
            float rc_ = pd * rcd, rd = pc * rcd;          // 1/pc, 1/pd
            float i0 = A.y * ra,  i1 = A.x * ra;
            float i2 = A.w * rb,  i3 = A.z * rb;
            float i4 = B4.y * rc_, i5 = B4.x * rc_;
            float i6 = B4.w * rd,  i7 = B4.z * rd;
            i0 *= i0; i1 *= i1; i2 *= i2; i3 *= i3;
            i4 *= i4; i5 *= i5; i6 *= i6; i7 *= i7;
            acc[r][g]     = make_float4(i0, i1, i2, i3);
            acc[r][g + 1] = make_float4(i4, i5, i6, i7);
            lsum += ((i0 + i1) + (i2 + i3)) + ((i4 + i5) + (i6 + i7));
        }

        // Warp reductions: row sum + lexicographic (dist, idx) argmin
        #pragma unroll
        for (int o = 16; o; o >>= 1) {
            lsum += __shfl_xor_sync(0xffffffffu, lsum, o);
            float om = __shfl_xor_sync(0xffffffffu, dmin, o);
            int   oi = __shfl_xor_sync(0xffffffffu, didx, o);
            if (om < dmin || (om == dmin && oi < didx)) { dmin = om; didx = oi; }
        }
        const float rS = 1.0f / lsum;

        // Normalized soft counts (coalesced float4 stores)
        float4* srow = (float4*)(scout + (size_t)(row0 + row) * KC);
        #pragma unroll
        for (int g = 0; g < 8; ++g) {
            float4 v = acc[r][g];
            v.x *= rS; v.y *= rS; v.z *= rS; v.w *= rS;
            srow[g * 32 + lane] = v;
        }

        // Quantized gather (codebook column didx, L2-resident) + loss partial
        const float* xr = Xs + row * DIM;
        float* qr = qout + (size_t)(row0 + row) * DIM;
        float lp = 0.f;
        #pragma unroll
        for (int i = 0; i < 8; ++i) {
            int d = lane + 32 * i;
            float q = cb[(size_t)d * KC + didx];
            qr[d] = q;
            float df = q - xr[d];
            lp = fmaf(df, df, lp);
        }
        warploss += lp;
    }

    #pragma unroll
    for (int o = 16; o; o >>= 1) warploss += __shfl_xor_sync(0xffffffffu, warploss, o);
    if (lane == 0) wl[warp] = warploss;
    __syncthreads();
    if (tid == 0) {
        float t = 0.f;
        #pragma unroll
        for (int i = 0; i < 8; ++i) t += wl[i];
        g_partials[blockIdx.x] = t;
    }
}

// ---------------------------------------------------------------- deterministic loss reduce
__global__ void finalize_kernel(float* __restrict__ lossout, int nparts, float scale) {
    __shared__ float s[256];
    float v = 0.f;
    for (int i = threadIdx.x; i < nparts; i += 256) v += g_partials[i];
    s[threadIdx.x] = v;
    __syncthreads();
    for (int o = 128; o; o >>= 1) {
        if (threadIdx.x < o) s[threadIdx.x] += s[threadIdx.x + o];
        __syncthreads();
    }
    if (threadIdx.x == 0) lossout[0] = s[0] * scale;
}

// ---------------------------------------------------------------- launch
extern "C" void kernel_launch(void* const* d_in, const int* in_sizes, int n_in,
                              void* d_out, int out_size) {
    const float* x  = (const float*)d_in[0];
    const float* cb = (const float*)d_in[1];
    int nx = in_sizes[0], nc = in_sizes[1];
    if (nx < nc) { const float* t = x; x = cb; cb = t; int ti = nx; nx = nc; nc = ti; }

    const int nrows = nx / DIM;              // 65536
    float* out     = (float*)d_out;
    float* qout    = out;                                    // [nrows, 256]
    float* scout   = out + (size_t)nrows * DIM;              // [nrows, 1024]
    float* lossout = scout + (size_t)nrows * KC;             // [1]

    const size_t SMEM = (size_t)(ROWS * DIM + KC + 2 * DK * KC) * sizeof(float);  // 164 KB
    cudaFuncSetAttribute(vq_main, cudaFuncAttributeMaxDynamicSharedMemorySize, (int)SMEM);

    cnorm_kernel<<<(KC + 255) / 256, 256>>>(cb);
    vq_main<<<nrows / ROWS, NTHREADS, SMEM>>>(x, cb, qout, scout);
    finalize_kernel<<<1, 256>>>(lossout, nrows / ROWS, 1.25f / (float)nx);
}

// round 6
// speedup vs baseline: 1.1469x; 1.1469x over previous
#include <cuda_runtime.h>
#include <cstdint>
#include <cstddef>

#define DIM      256
#define KC       1024
#define ROWS     32
#define DK       16
#define NTHREADS 256

typedef unsigned long long ull;

__device__ float g_cnorm[KC];
__device__ float g_partials[4096];

__device__ __forceinline__ void cpa16(void* sdst, const void* gsrc) {
    uint32_t s = (uint32_t)__cvta_generic_to_shared(sdst);
    asm volatile("cp.async.ca.shared.global [%0], [%1], 16;\n" :: "r"(s), "l"(gsrc));
}
__device__ __forceinline__ float frcp(float x) {
    float r; asm("rcp.approx.ftz.f32 %0, %1;" : "=f"(r) : "f"(x)); return r;
}
// Packed fp32x2 FMA (sm_103a FFMA2): acc = a*b + acc, lane-wise, rn semantics.
__device__ __forceinline__ void ffma2(ull& acc, ull a, ull b) {
    asm("fma.rn.f32x2 %0, %1, %2, %0;" : "+l"(acc) : "l"(a), "l"(b));
}
__device__ __forceinline__ ull pack2(float x) {
    ull r; asm("mov.b64 %0, {%1, %1};" : "=l"(r) : "f"(x)); return r;
}
__device__ __forceinline__ float2 unpack2(ull v) {
    float2 r; asm("mov.b64 {%0, %1}, %2;" : "=f"(r.x), "=f"(r.y) : "l"(v)); return r;
}

// ---------------------------------------------------------------- codebook column norms
// 32 blocks x 32 cols; block threads = (dseg 0..7) x (col 0..31); two-level reduce.
__global__ void cnorm_kernel(const float* __restrict__ cb) {
    __shared__ float s[8][32];
    const int c = threadIdx.x & 31, dseg = threadIdx.x >> 5;
    const int col = blockIdx.x * 32 + c;
    float sum = 0.f;
    #pragma unroll
    for (int k = 0; k < 32; ++k) {
        int d = dseg * 32 + k;
        float v = cb[(size_t)d * KC + col];
        sum = fmaf(v, v, sum);
    }
    s[dseg][c] = sum;
    __syncthreads();
    if (threadIdx.x < 32) {
        float t = 0.f;
        #pragma unroll
        for (int i = 0; i < 8; ++i) t += s[i][threadIdx.x];
        g_cnorm[blockIdx.x * 32 + threadIdx.x] = t;
    }
}

// ---------------------------------------------------------------- fused VQ kernel
// CTA: 32 rows x 1024 codes. Thread tile: 4 rows x 32 cols (cols = g*128 + 4*lane + k).
// Accumulators held as fp32x2 pairs: acc[r][2g] = cols (base,base+1), acc[r][2g+1] = (base+2,base+3).
__global__ __launch_bounds__(NTHREADS, 1)
void vq_main(const float* __restrict__ x, const float* __restrict__ cb,
             float* __restrict__ qout, float* __restrict__ scout) {
    extern __shared__ float sm[];
    float* Xs = sm;                 // ROWS*DIM   = 8192 floats
    float* CN = Xs + ROWS * DIM;    // KC         = 1024 floats
    float* Ct = CN + KC;            // 2*DK*KC    = 32768 floats
    __shared__ float wl[8];

    const int tid  = threadIdx.x;
    const int warp = tid >> 5, lane = tid & 31;
    const int row0 = blockIdx.x * ROWS;

    // Load X tile (32 rows x 256 = one contiguous 32KB block)
    {
        const float4* src = (const float4*)(x + (size_t)row0 * DIM);
        float4* dst = (float4*)Xs;
        #pragma unroll
        for (int i = 0; i < 8; ++i) dst[tid + i * NTHREADS] = src[tid + i * NTHREADS];
    }
    __syncthreads();

    // Per-row ||x||^2 (warp w owns rows 4w..4w+3)
    float xn[4];
    #pragma unroll
    for (int r = 0; r < 4; ++r) {
        const float* xr = Xs + (warp * 4 + r) * DIM;
        float s = 0.f;
        #pragma unroll
        for (int i = 0; i < 8; ++i) { float v = xr[lane + 32 * i]; s = fmaf(v, v, s); }
        #pragma unroll
        for (int o = 16; o; o >>= 1) s += __shfl_xor_sync(0xffffffffu, s, o);
        xn[r] = s;
    }

    ull acc[4][16];
    #pragma unroll
    for (int r = 0; r < 4; ++r)
        #pragma unroll
        for (int j = 0; j < 16; ++j) acc[r][j] = 0ull;

    // Prologue: async-load codebook chunk 0
    {
        const float4* src = (const float4*)cb;
        float4* dst = (float4*)Ct;
        #pragma unroll
        for (int i = 0; i < 16; ++i) cpa16(dst + tid + i * NTHREADS, src + tid + i * NTHREADS);
        asm volatile("cp.async.commit_group;\n");
    }

    const int NCHUNK = DIM / DK;   // 16
    for (int c = 0; c < NCHUNK; ++c) {
        if (c + 1 < NCHUNK) {
            const float4* src = (const float4*)(cb + (size_t)(c + 1) * DK * KC);
            float4* dst = (float4*)(Ct + ((c + 1) & 1) * DK * KC);
            #pragma unroll
            for (int i = 0; i < 16; ++i) cpa16(dst + tid + i * NTHREADS, src + tid + i * NTHREADS);
            asm volatile("cp.async.commit_group;\n");
            asm volatile("cp.async.wait_group 1;\n");
        } else {
            asm volatile("cp.async.wait_group 0;\n");
        }
        __syncthreads();

        const float* B  = Ct + (c & 1) * DK * KC;
        const float* Xb = Xs + warp * 4 * DIM + c * DK;
        #pragma unroll 4
        for (int dd = 0; dd < DK; ++dd) {
            ull A0 = pack2(Xb[dd]);
            ull A1 = pack2(Xb[DIM + dd]);
            ull A2 = pack2(Xb[2 * DIM + dd]);
            ull A3 = pack2(Xb[3 * DIM + dd]);
            const ulonglong2* Bd = (const ulonglong2*)(B + dd * KC);
            #pragma unroll
            for (int g = 0; g < 8; ++g) {
                ulonglong2 b = Bd[g * 32 + lane];
                ffma2(acc[0][2 * g], A0, b.x); ffma2(acc[0][2 * g + 1], A0, b.y);
                ffma2(acc[1][2 * g], A1, b.x); ffma2(acc[1][2 * g + 1], A1, b.y);
                ffma2(acc[2][2 * g], A2, b.x); ffma2(acc[2][2 * g + 1], A2, b.y);
                ffma2(acc[3][2 * g], A3, b.x); ffma2(acc[3][2 * g + 1], A3, b.y);
            }
        }
        __syncthreads();
    }

    // Codebook col norms for this lane's columns (loaded late: not needed until epilogue)
    #pragma unroll
    for (int i = 0; i < 4; ++i) CN[tid + i * NTHREADS] = g_cnorm[tid + i * NTHREADS];
    __syncthreads();
    float4 cn4[8];
    #pragma unroll
    for (int g = 0; g < 8; ++g) cn4[g] = ((const float4*)CN)[g * 32 + lane];

    float warploss = 0.f;
    #pragma unroll
    for (int r = 0; r < 4; ++r) {
        const int row = warp * 4 + r;
        const float xnr = xn[r];
        float dmin = 3.4e38f; int didx = 0;
        float4 dv[8];

        // sim -> dist. Ascending col order within lane + strict '<'
        // keeps the lowest tied index (matches jnp.argmin).
        #pragma unroll
        for (int g = 0; g < 8; ++g) {
            float2 p0 = unpack2(acc[r][2 * g]);
            float2 p1 = unpack2(acc[r][2 * g + 1]);
            float4 d4 = make_float4(p0.x, p0.y, p1.x, p1.y);
            float4 c4 = cn4[g];
            int cbse = g * 128 + lane * 4;
            d4.x = fmaf(-2.f, d4.x, xnr + c4.x);
            d4.y = fmaf(-2.f, d4.y, xnr + c4.y);
            d4.z = fmaf(-2.f, d4.z, xnr + c4.z);
            d4.w = fmaf(-2.f, d4.w, xnr + c4.w);
            if (d4.x < dmin) { dmin = d4.x; didx = cbse + 0; }
            if (d4.y < dmin) { dmin = d4.y; didx = cbse + 1; }
            if (d4.z < dmin) { dmin = d4.z; didx = cbse + 2; }
            if (d4.w < dmin) { dmin = d4.w; didx = cbse + 3; }
            dv[g] = d4;
        }

        // Batched reciprocal: 1 MUFU per 8 values, then inv^2, accumulate row sum.
        float lsum = 0.f;
        #pragma unroll
        for (int g = 0; g < 8; g += 2) {
            float4 A = dv[g], B4 = dv[g + 1];
            float pa = A.x * A.y, pb = A.z * A.w, pc = B4.x * B4.y, pd = B4.z * B4.w;
            float pab = pa * pb, pcd = pc * pd;
            float R   = frcp(pab * pcd);
            float rab = pcd * R, rcd = pab * R;          // 1/pab, 1/pcd
            float ra  = pb * rab, rb = pa * rab;          // 1/pa, 1/pb
            float rc_ = pd * rcd, rd = pc * rcd;          // 1/pc, 1/pd
            float i0 = A.y * ra,  i1 = A.x * ra;
            float i2 = A.w * rb,  i3 = A.z * rb;
            float i4 = B4.y * rc_, i5 = B4.x * rc_;
            float i6 = B4.w * rd,  i7 = B4.z * rd;
            i0 *= i0; i1 *= i1; i2 *= i2; i3 *= i3;
            i4 *= i4; i5 *= i5; i6 *= i6; i7 *= i7;
            dv[g]     = make_float4(i0, i1, i2, i3);
            dv[g + 1] = make_float4(i4, i5, i6, i7);
            lsum += ((i0 + i1) + (i2 + i3)) + ((i4 + i5) + (i6 + i7));
        }

        // Warp reductions: row sum + lexicographic (dist, idx) argmin
        #pragma unroll
        for (int o = 16; o; o >>= 1) {
            lsum += __shfl_xor_sync(0xffffffffu, lsum, o);
            float om = __shfl_xor_sync(0xffffffffu, dmin, o);
            int   oi = __shfl_xor_sync(0xffffffffu, didx, o);
            if (om < dmin || (om == dmin && oi < didx)) { dmin = om; didx = oi; }
        }
        const float rS = 1.0f / lsum;

        // Normalized soft counts (coalesced float4 stores)
        float4* srow = (float4*)(scout + (size_t)(row0 + row) * KC);
        #pragma unroll
        for (int g = 0; g < 8; ++g) {
            float4 v = dv[g];
            v.x *= rS; v.y *= rS; v.z *= rS; v.w *= rS;
            srow[g * 32 + lane] = v;
        }

        // Quantized gather (codebook column didx, L2-resident) + loss partial
        const float* xr = Xs + row * DIM;
        float* qr = qout + (size_t)(row0 + row) * DIM;
        float lp = 0.f;
        #pragma unroll
        for (int i = 0; i < 8; ++i) {
            int d = lane + 32 * i;
            float q = cb[(size_t)d * KC + didx];
            qr[d] = q;
            float df = q - xr[d];
            lp = fmaf(df, df, lp);
        }
        warploss += lp;
    }

    #pragma unroll
    for (int o = 16; o; o >>= 1) warploss += __shfl_xor_sync(0xffffffffu, warploss, o);
    if (lane == 0) wl[warp] = warploss;
    __syncthreads();
    if (tid == 0) {
        float t = 0.f;
        #pragma unroll
        for (int i = 0; i < 8; ++i) t += wl[i];
        g_partials[blockIdx.x] = t;
    }
}

// ---------------------------------------------------------------- deterministic loss reduce
__global__ void finalize_kernel(float* __restrict__ lossout, int nparts, float scale) {
    __shared__ float s[256];
    float v = 0.f;
    for (int i = threadIdx.x; i < nparts; i += 256) v += g_partials[i];
    s[threadIdx.x] = v;
    __syncthreads();
    for (int o = 128; o; o >>= 1) {
        if (threadIdx.x < o) s[threadIdx.x] += s[threadIdx.x + o];
        __syncthreads();
    }
    if (threadIdx.x == 0) lossout[0] = s[0] * scale;
}

// ---------------------------------------------------------------- launch
extern "C" void kernel_launch(void* const* d_in, const int* in_sizes, int n_in,
                              void* d_out, int out_size) {
    const float* x  = (const float*)d_in[0];
    const float* cb = (const float*)d_in[1];
    int nx = in_sizes[0], nc = in_sizes[1];
    if (nx < nc) { const float* t = x; x = cb; cb = t; int ti = nx; nx = nc; nc = ti; }

    const int nrows = nx / DIM;              // 65536
    float* out     = (float*)d_out;
    float* qout    = out;                                    // [nrows, 256]
    float* scout   = out + (size_t)nrows * DIM;              // [nrows, 1024]
    float* lossout = scout + (size_t)nrows * KC;             // [1]

    const size_t SMEM = (size_t)(ROWS * DIM + KC + 2 * DK * KC) * sizeof(float);  // 164 KB
    cudaFuncSetAttribute(vq_main, cudaFuncAttributeMaxDynamicSharedMemorySize, (int)SMEM);

    cnorm_kernel<<<32, 256>>>(cb);
    vq_main<<<nrows / ROWS, NTHREADS, SMEM>>>(x, cb, qout, scout);
    finalize_kernel<<<1, 256>>>(lossout, nrows / ROWS, 1.25f / (float)nx);
}